// round 9
// baseline (speedup 1.0000x reference)
#include <cuda_runtime.h>
#include <cstddef>

// GeometricEdgeConv: B=8, N=16384, C=128, OUT=128, K=16
// out = leaky_relu( x @ Ws + [mean_k nbr_x, pos_i - mean_k nbr_pos, mean_k d2] @ We , 0.2 )
// Linearity: average features BEFORE the matvec (16x fewer FLOPs).
// R6: 128 threads/CTA, 4pts x 16cols per thread (halves per-point B smem traffic),
//     3 CTAs/SM, packed fma.rn.f32x2 inner loop.

#define BN      8
#define NPTS    16384
#define NSHIFT  14
#define CIN     128
#define COUT    128
#define KNB     16
#define P_TOTAL (BN * NPTS)   // 131072

#define TILE_M    64
#define THREADS   128
#define KREAL     260
#define KTOT      264
#define AS_STRIDE 268
#define KT        8
#define NTILES    (KTOT / KT) // 33

// ---- packed f32x2 helpers (sm_103a) ----
__device__ __forceinline__ void ffma2(unsigned long long& d,
                                      unsigned long long a,
                                      unsigned long long b)
{
    asm("fma.rn.f32x2 %0, %1, %2, %0;" : "+l"(d) : "l"(a), "l"(b));
}
__device__ __forceinline__ unsigned long long bcast2(float a)
{
    unsigned long long r;
    asm("mov.b64 %0, {%1, %1};" : "=l"(r) : "f"(a));
    return r;
}
__device__ __forceinline__ void unpack2(float& lo, float& hi, unsigned long long v)
{
    asm("mov.b64 {%0, %1}, %2;" : "=f"(lo), "=f"(hi) : "l"(v));
}

// combined weight row k of [264][128]: w_self (k<128), w_edge (128<=k<260), else 0
__device__ __forceinline__ float4 load_w(const float* __restrict__ w_self,
                                         const float* __restrict__ w_edge,
                                         int k, int lo)
{
    if (k < CIN)
        return *reinterpret_cast<const float4*>(w_self + (size_t)k * COUT + lo);
    else if (k < KREAL)
        return *reinterpret_cast<const float4*>(w_edge + (size_t)(k - CIN) * COUT + lo);
    return make_float4(0.f, 0.f, 0.f, 0.f);
}

__global__ __launch_bounds__(THREADS, 3)
void gec_kernel(const float* __restrict__ x,
                const float* __restrict__ pos,
                const int*   __restrict__ idx,
                const float* __restrict__ w_self,
                const float* __restrict__ w_edge,
                float*       __restrict__ out)
{
    extern __shared__ float smem[];
    float* As = smem;                          // [TILE_M][AS_STRIDE]
    float* Bs = smem + TILE_M * AS_STRIDE;     // [KT][COUT]

    const int tid  = threadIdx.x;
    const int lane = tid & 31;
    const int warp = tid >> 5;                 // 0..3
    const int g0   = blockIdx.x * TILE_M;

    // ---------------- Phase 1a: stage own x rows into As[:, 0:128] ----------------
    #pragma unroll
    for (int it = 0; it < 16; ++it) {
        int f4 = tid + it * THREADS;           // 0..2047 ; 32 float4 per row
        int p  = f4 >> 5;
        int c4 = f4 & 31;
        float4 v = *(reinterpret_cast<const float4*>(x + (size_t)(g0 + p) * CIN) + c4);
        float* dst = As + p * AS_STRIDE + c4 * 4;
        dst[0] = v.x; dst[1] = v.y; dst[2] = v.z; dst[3] = v.w;
    }

    // ---------------- Phase 1b: warp-per-point coalesced gather ----------------
    // Warp w handles points p = w*16 .. w*16+15; full warp loads each neighbor's 512B row.
    {
        const int l16 = lane & 15;
        #pragma unroll
        for (int i = 0; i < 16; ++i) {
            const int p  = warp * 16 + i;
            const int gp = g0 + p;
            const int b  = gp >> NSHIFT;
            const float* xb   = x   + (((size_t)b << NSHIFT)) * CIN;
            const float* posb = pos + (((size_t)b << NSHIFT)) * 3;

            int my = idx[(size_t)gp * KNB + l16];   // lanes 16-31 duplicate 0-15

            float4 acc = make_float4(0.f, 0.f, 0.f, 0.f);
            #pragma unroll
            for (int k = 0; k < KNB; ++k) {
                int n = __shfl_sync(0xffffffffu, my, k);
                float4 v = *(reinterpret_cast<const float4*>(xb + (size_t)n * CIN) + lane);
                acc.x += v.x; acc.y += v.y; acc.z += v.z; acc.w += v.w;
            }

            float px = pos[(size_t)gp * 3 + 0];
            float py = pos[(size_t)gp * 3 + 1];
            float pz = pos[(size_t)gp * 3 + 2];
            float rx = 0.f, ry = 0.f, rz = 0.f, rd = 0.f;
            if (lane < KNB) {
                const float* nb = posb + (size_t)my * 3;
                float ax = px - nb[0], ay = py - nb[1], az = pz - nb[2];
                rx = ax; ry = ay; rz = az;
                rd = ax * ax + ay * ay + az * az;
            }
            #pragma unroll
            for (int s = 8; s >= 1; s >>= 1) {
                rx += __shfl_xor_sync(0xffffffffu, rx, s, 16);
                ry += __shfl_xor_sync(0xffffffffu, ry, s, 16);
                rz += __shfl_xor_sync(0xffffffffu, rz, s, 16);
                rd += __shfl_xor_sync(0xffffffffu, rd, s, 16);
            }

            const float sc = 1.0f / 16.0f;
            float* dst = As + p * AS_STRIDE + CIN + lane * 4;
            *reinterpret_cast<float4*>(dst) =
                make_float4(acc.x * sc, acc.y * sc, acc.z * sc, acc.w * sc);

            if (lane == 0) {
                float* gq = As + p * AS_STRIDE + 256;
                gq[0] = rx * sc; gq[1] = ry * sc; gq[2] = rz * sc; gq[3] = rd * sc;
                gq[4] = 0.f; gq[5] = 0.f; gq[6] = 0.f; gq[7] = 0.f;   // pad 260..263
            }
        }
    }

    // ---------------- Phase 2: GEMM  C[64][128] = As[64][264] * W[264][128] ----------------
    // thread -> 4 points x 16 cols
    const int tx = tid & 7;     // cols tx*16 .. tx*16+15
    const int ty = tid >> 3;    // points ty*4 .. ty*4+3

    unsigned long long accp[4][8];
    #pragma unroll
    for (int i = 0; i < 4; ++i)
        #pragma unroll
        for (int j = 0; j < 8; ++j) accp[i][j] = 0ull;

    // Bs loader: thread loads rows r0 = tid>>5 and r0+4, col4 = tid&31
    const int r0 = tid >> 5;
    const int c4 = (tid & 31) * 4;

    float4 pre0 = load_w(w_self, w_edge, r0,     c4);
    float4 pre1 = load_w(w_self, w_edge, r0 + 4, c4);

    for (int kt = 0; kt < NTILES; ++kt) {
        __syncthreads();                       // Bs free (first iter: fences Phase 1)
        *reinterpret_cast<float4*>(Bs + r0 * COUT + c4)       = pre0;
        *reinterpret_cast<float4*>(Bs + (r0 + 4) * COUT + c4) = pre1;
        __syncthreads();                       // Bs ready

        if (kt + 1 < NTILES) {
            int kb = (kt + 1) * KT;
            pre0 = load_w(w_self, w_edge, kb + r0,     c4);
            pre1 = load_w(w_self, w_edge, kb + r0 + 4, c4);
        }

        // A: 2 x LDS.128 per point along k (broadcast across tx lanes)
        float4 av0[4], av1[4];
        #pragma unroll
        for (int i = 0; i < 4; ++i) {
            const float* ar = As + (ty * 4 + i) * AS_STRIDE + kt * KT;
            av0[i] = *reinterpret_cast<const float4*>(ar);
            av1[i] = *reinterpret_cast<const float4*>(ar + 4);
        }

        #pragma unroll
        for (int kk = 0; kk < KT; ++kk) {
            const ulonglong2* brow =
                reinterpret_cast<const ulonglong2*>(Bs + kk * COUT + tx * 16);
            ulonglong2 q0 = brow[0];   // cols 0-3
            ulonglong2 q1 = brow[1];   // cols 4-7
            ulonglong2 q2 = brow[2];   // cols 8-11
            ulonglong2 q3 = brow[3];   // cols 12-15

            #pragma unroll
            for (int i = 0; i < 4; ++i) {
                float a;
                switch (kk) {
                    case 0: a = av0[i].x; break;
                    case 1: a = av0[i].y; break;
                    case 2: a = av0[i].z; break;
                    case 3: a = av0[i].w; break;
                    case 4: a = av1[i].x; break;
                    case 5: a = av1[i].y; break;
                    case 6: a = av1[i].z; break;
                    default: a = av1[i].w; break;
                }
                unsigned long long aa = bcast2(a);
                ffma2(accp[i][0], aa, q0.x);
                ffma2(accp[i][1], aa, q0.y);
                ffma2(accp[i][2], aa, q1.x);
                ffma2(accp[i][3], aa, q1.y);
                ffma2(accp[i][4], aa, q2.x);
                ffma2(accp[i][5], aa, q2.y);
                ffma2(accp[i][6], aa, q3.x);
                ffma2(accp[i][7], aa, q3.y);
            }
        }
    }

    // ---------------- Epilogue: unpack + leaky_relu(0.2) + float4 stores ----------------
    #pragma unroll
    for (int i = 0; i < 4; ++i) {
        int p = ty * 4 + i;
        float* op = out + (size_t)(g0 + p) * COUT + tx * 16;
        float r[16];
        #pragma unroll
        for (int j = 0; j < 8; ++j)
            unpack2(r[2 * j], r[2 * j + 1], accp[i][j]);
        #pragma unroll
        for (int q = 0; q < 4; ++q) {
            float4 o;
            float v;
            v = r[4 * q + 0]; o.x = v > 0.f ? v : 0.2f * v;
            v = r[4 * q + 1]; o.y = v > 0.f ? v : 0.2f * v;
            v = r[4 * q + 2]; o.z = v > 0.f ? v : 0.2f * v;
            v = r[4 * q + 3]; o.w = v > 0.f ? v : 0.2f * v;
            *reinterpret_cast<float4*>(op + 4 * q) = o;
        }
    }
}

extern "C" void kernel_launch(void* const* d_in, const int* in_sizes, int n_in,
                              void* d_out, int out_size)
{
    const float* x      = (const float*)d_in[0];
    const float* pos    = (const float*)d_in[1];
    const int*   idx    = (const int*)  d_in[2];
    const float* w_self = (const float*)d_in[3];
    const float* w_edge = (const float*)d_in[4];
    float* out = (float*)d_out;

    size_t smem_bytes = (size_t)(TILE_M * AS_STRIDE + KT * COUT) * sizeof(float); // 72704 B
    cudaFuncSetAttribute(gec_kernel, cudaFuncAttributeMaxDynamicSharedMemorySize,
                         (int)smem_bytes);

    gec_kernel<<<P_TOTAL / TILE_M, THREADS, smem_bytes>>>(x, pos, idx, w_self, w_edge, out);
}

// round 11
// speedup vs baseline: 2.1509x; 2.1509x over previous
#include <cuda_runtime.h>
#include <cstddef>

// GeometricEdgeConv: B=8, N=16384, C=128, OUT=128, K=16
// out = leaky_relu( x @ Ws + [mean nbr_x, pos_i - mean nbr_pos, mean d2] @ We, 0.2 )
// R9: TILE_M=128, 256 thr, 8pts x 8cols/thread; W pre-packed to __device__ global,
//     B read via L1-cached LDG (no Bs smem, no barriers in GEMM loop), fma.rn.f32x2.

#define BN      8
#define NPTS    16384
#define NSHIFT  14
#define CIN     128
#define COUT    128
#define KNB     16
#define P_TOTAL (BN * NPTS)   // 131072

#define TILE_M    128
#define THREADS   256
#define KREAL     260
#define KTOT      264
#define AS_STRIDE 268
#define KT        8
#define NTILES    (KTOT / KT) // 33

// packed combined weight matrix [KTOT][COUT], rows >= KREAL are zero
__device__ float Wpack[KTOT * COUT];

__global__ void pack_w_kernel(const float* __restrict__ w_self,
                              const float* __restrict__ w_edge)
{
    int i = blockIdx.x * blockDim.x + threadIdx.x;
    if (i >= KTOT * COUT) return;
    int k = i >> 7;           // / COUT
    int c = i & (COUT - 1);
    float v = 0.f;
    if (k < CIN)        v = w_self[(size_t)k * COUT + c];
    else if (k < KREAL) v = w_edge[(size_t)(k - CIN) * COUT + c];
    Wpack[i] = v;
}

// ---- packed f32x2 helpers (sm_103a) ----
__device__ __forceinline__ void ffma2(unsigned long long& d,
                                      unsigned long long a,
                                      unsigned long long b)
{
    asm("fma.rn.f32x2 %0, %1, %2, %0;" : "+l"(d) : "l"(a), "l"(b));
}
__device__ __forceinline__ unsigned long long bcast2(float a)
{
    unsigned long long r;
    asm("mov.b64 %0, {%1, %1};" : "=l"(r) : "f"(a));
    return r;
}
__device__ __forceinline__ void unpack2(float& lo, float& hi, unsigned long long v)
{
    asm("mov.b64 {%0, %1}, %2;" : "=f"(lo), "=f"(hi) : "l"(v));
}

__global__ __launch_bounds__(THREADS, 1)
void gec_kernel(const float* __restrict__ x,
                const float* __restrict__ pos,
                const int*   __restrict__ idx,
                float*       __restrict__ out)
{
    extern __shared__ float smem[];
    float* As = smem;                          // [TILE_M][AS_STRIDE]

    const int tid  = threadIdx.x;
    const int lane = tid & 31;
    const int warp = tid >> 5;                 // 0..7
    const int g0   = blockIdx.x * TILE_M;

    // ---------------- Phase 1a: stage own x rows into As[:, 0:128] ----------------
    #pragma unroll
    for (int it = 0; it < 16; ++it) {
        int f4 = tid + it * THREADS;           // 0..4095 ; 32 float4 per row
        int p  = f4 >> 5;
        int c4 = f4 & 31;
        float4 v = *(reinterpret_cast<const float4*>(x + (size_t)(g0 + p) * CIN) + c4);
        float* dst = As + p * AS_STRIDE + c4 * 4;
        dst[0] = v.x; dst[1] = v.y; dst[2] = v.z; dst[3] = v.w;
    }

    // ---------------- Phase 1b: warp-per-point coalesced gather ----------------
    // Warp w handles points p = w*16 .. w*16+15; full warp loads each neighbor's
    // contiguous 512B feature row (4 lines per LDG.128).
    {
        const int l16 = lane & 15;
        #pragma unroll
        for (int i = 0; i < 16; ++i) {
            const int p  = warp * 16 + i;
            const int gp = g0 + p;
            const int b  = gp >> NSHIFT;
            const float* xb   = x   + (((size_t)b << NSHIFT)) * CIN;
            const float* posb = pos + (((size_t)b << NSHIFT)) * 3;

            int my = idx[(size_t)gp * KNB + l16];   // lanes 16-31 duplicate 0-15

            float4 acc = make_float4(0.f, 0.f, 0.f, 0.f);
            #pragma unroll
            for (int k = 0; k < KNB; ++k) {
                int n = __shfl_sync(0xffffffffu, my, k);
                float4 v = *(reinterpret_cast<const float4*>(xb + (size_t)n * CIN) + lane);
                acc.x += v.x; acc.y += v.y; acc.z += v.z; acc.w += v.w;
            }

            float px = pos[(size_t)gp * 3 + 0];
            float py = pos[(size_t)gp * 3 + 1];
            float pz = pos[(size_t)gp * 3 + 2];
            float rx = 0.f, ry = 0.f, rz = 0.f, rd = 0.f;
            if (lane < KNB) {
                const float* nb = posb + (size_t)my * 3;
                float ax = px - nb[0], ay = py - nb[1], az = pz - nb[2];
                rx = ax; ry = ay; rz = az;
                rd = ax * ax + ay * ay + az * az;
            }
            #pragma unroll
            for (int s = 8; s >= 1; s >>= 1) {
                rx += __shfl_xor_sync(0xffffffffu, rx, s, 16);
                ry += __shfl_xor_sync(0xffffffffu, ry, s, 16);
                rz += __shfl_xor_sync(0xffffffffu, rz, s, 16);
                rd += __shfl_xor_sync(0xffffffffu, rd, s, 16);
            }

            const float sc = 1.0f / 16.0f;
            float* dst = As + p * AS_STRIDE + CIN + lane * 4;
            *reinterpret_cast<float4*>(dst) =
                make_float4(acc.x * sc, acc.y * sc, acc.z * sc, acc.w * sc);

            if (lane == 0) {
                float* gq = As + p * AS_STRIDE + 256;
                gq[0] = rx * sc; gq[1] = ry * sc; gq[2] = rz * sc; gq[3] = rd * sc;
                gq[4] = 0.f; gq[5] = 0.f; gq[6] = 0.f; gq[7] = 0.f;   // pad 260..263
            }
        }
    }

    __syncthreads();   // the ONLY barrier: As complete before GEMM

    // ------------- Phase 2: GEMM  C[128][128] = As[128][264] * Wpack[264][128] -------------
    // thread -> 8 points x 8 cols; B via L1-cached LDG.128, no smem staging.
    const int tx = tid & 15;    // cols tx*8 .. tx*8+7
    const int ty = tid >> 4;    // points ty*8 .. ty*8+7

    unsigned long long accp[8][4];
    #pragma unroll
    for (int i = 0; i < 8; ++i)
        #pragma unroll
        for (int j = 0; j < 4; ++j) accp[i][j] = 0ull;

    const float* arow0 = As + (ty * 8) * AS_STRIDE;

    for (int kt = 0; kt < NTILES; ++kt) {
        // A fragment: 8 points x 8 k  (2 x LDS.128 per point, 2-address broadcast/warp)
        float4 a0[8], a1[8];
        #pragma unroll
        for (int i = 0; i < 8; ++i) {
            const float* ar = arow0 + i * AS_STRIDE + kt * KT;
            a0[i] = *reinterpret_cast<const float4*>(ar);
            a1[i] = *reinterpret_cast<const float4*>(ar + 4);
        }

        #pragma unroll
        for (int kk = 0; kk < KT; ++kk) {
            const ulonglong2* wr = reinterpret_cast<const ulonglong2*>(
                Wpack + (size_t)(kt * KT + kk) * COUT + tx * 8);
            ulonglong2 b0 = wr[0];   // cols 0-3 as two packed pairs
            ulonglong2 b1 = wr[1];   // cols 4-7

            #pragma unroll
            for (int i = 0; i < 8; ++i) {
                float a;
                switch (kk) {
                    case 0: a = a0[i].x; break;
                    case 1: a = a0[i].y; break;
                    case 2: a = a0[i].z; break;
                    case 3: a = a0[i].w; break;
                    case 4: a = a1[i].x; break;
                    case 5: a = a1[i].y; break;
                    case 6: a = a1[i].z; break;
                    default: a = a1[i].w; break;
                }
                unsigned long long aa = bcast2(a);
                ffma2(accp[i][0], aa, b0.x);
                ffma2(accp[i][1], aa, b0.y);
                ffma2(accp[i][2], aa, b1.x);
                ffma2(accp[i][3], aa, b1.y);
            }
        }
    }

    // ---------------- Epilogue: unpack + leaky_relu(0.2) + float4 stores ----------------
    #pragma unroll
    for (int i = 0; i < 8; ++i) {
        int p = ty * 8 + i;
        float* op = out + (size_t)(g0 + p) * COUT + tx * 8;
        float r[8];
        unpack2(r[0], r[1], accp[i][0]);
        unpack2(r[2], r[3], accp[i][1]);
        unpack2(r[4], r[5], accp[i][2]);
        unpack2(r[6], r[7], accp[i][3]);
        float4 o0, o1;
        float v;
        v = r[0]; o0.x = v > 0.f ? v : 0.2f * v;
        v = r[1]; o0.y = v > 0.f ? v : 0.2f * v;
        v = r[2]; o0.z = v > 0.f ? v : 0.2f * v;
        v = r[3]; o0.w = v > 0.f ? v : 0.2f * v;
        v = r[4]; o1.x = v > 0.f ? v : 0.2f * v;
        v = r[5]; o1.y = v > 0.f ? v : 0.2f * v;
        v = r[6]; o1.z = v > 0.f ? v : 0.2f * v;
        v = r[7]; o1.w = v > 0.f ? v : 0.2f * v;
        *reinterpret_cast<float4*>(op)     = o0;
        *reinterpret_cast<float4*>(op + 4) = o1;
    }
}

extern "C" void kernel_launch(void* const* d_in, const int* in_sizes, int n_in,
                              void* d_out, int out_size)
{
    const float* x      = (const float*)d_in[0];
    const float* pos    = (const float*)d_in[1];
    const int*   idx    = (const int*)  d_in[2];
    const float* w_self = (const float*)d_in[3];
    const float* w_edge = (const float*)d_in[4];
    float* out = (float*)d_out;

    pack_w_kernel<<<(KTOT * COUT + 255) / 256, 256>>>(w_self, w_edge);

    size_t smem_bytes = (size_t)(TILE_M * AS_STRIDE) * sizeof(float); // 137216 B
    cudaFuncSetAttribute(gec_kernel, cudaFuncAttributeMaxDynamicSharedMemorySize,
                         (int)smem_bytes);

    gec_kernel<<<P_TOTAL / TILE_M, THREADS, smem_bytes>>>(x, pos, idx, out);
}